// round 6
// baseline (speedup 1.0000x reference)
#include <cuda_runtime.h>
#include <cstdint>

// Problem constants
#define BB 1024
#define TT 4096
#define LL 30
#define HH 32
#define PP 2

typedef unsigned long long u64;

// ---------------------------------------------------------------------------
// Scalar MUFU pieces (abs err ~1e-7): tanh(x) = 1 - 2/(exp2(2*log2e*x)+1)
// ---------------------------------------------------------------------------
__device__ __forceinline__ float ex2f(float x) {
    float r; asm("ex2.approx.ftz.f32 %0, %1;" : "=f"(r) : "f"(x)); return r;
}
__device__ __forceinline__ float rcpf(float x) {
    float r; asm("rcp.approx.ftz.f32 %0, %1;" : "=f"(r) : "f"(x)); return r;
}
__device__ __forceinline__ float tanh_acc(float x) {
    const float C = 2.885390081777927f;  // 2*log2(e)
    float e = ex2f(fminf(x * C, 30.0f));
    return 1.0f - 2.0f * rcpf(e + 1.0f);
}

// ---------------------------------------------------------------------------
// Packed f32x2 ops (FFMA2 — only reachable via PTX) and pack/unpack movs
// ---------------------------------------------------------------------------
__device__ __forceinline__ u64 pk2(float lo, float hi) {
    u64 r; asm("mov.b64 %0, {%1, %2};" : "=l"(r) : "f"(lo), "f"(hi)); return r;
}
__device__ __forceinline__ void upk2(u64 v, float& lo, float& hi) {
    asm("mov.b64 {%0, %1}, %2;" : "=f"(lo), "=f"(hi) : "l"(v));
}
__device__ __forceinline__ u64 fma2(u64 a, u64 b, u64 c) {
    u64 r; asm("fma.rn.f32x2 %0, %1, %2, %3;" : "=l"(r) : "l"(a), "l"(b), "l"(c)); return r;
}
__device__ __forceinline__ u64 mul2(u64 a, u64 b) {
    u64 r; asm("mul.rn.f32x2 %0, %1, %2;" : "=l"(r) : "l"(a), "l"(b)); return r;
}
__device__ __forceinline__ u64 add2(u64 a, u64 b) {
    u64 r; asm("add.rn.f32x2 %0, %1, %2;" : "=l"(r) : "l"(a), "l"(b)); return r;
}

// 8-lane sum, broadcast to all lanes: flat shfl(1,2,3) + add tree + xor4.
// 4 shuffles, chain = 2 shuffle latencies.
__device__ __forceinline__ float gsum8(float v) {
    float s1 = __shfl_xor_sync(0xffffffffu, v, 1);
    float s2 = __shfl_xor_sync(0xffffffffu, v, 2);
    float s3 = __shfl_xor_sync(0xffffffffu, v, 3);
    float t = (v + s1) + (s2 + s3);
    t += __shfl_xor_sync(0xffffffffu, t, 4);
    return t;
}

// ---------------------------------------------------------------------------
// Kernel 1: encoder + sequential Euler scan.
// 8 lanes per chain group, and each thread carries TWO independent batch
// chains (A/B), explicitly interleaved inside STEP2 so chain-A's MUFU/SHFL
// latency is hidden by chain-B's issue stream (and vice versa).
// 128 blocks x 32 threads -> 128 warps, one per SMSP on 128 SMs.
// ---------------------------------------------------------------------------
__global__ void __launch_bounds__(32, 1)
scan_kernel(const float* __restrict__ x,
            const float* __restrict__ ew1, const float* __restrict__ eb1,
            const float* __restrict__ ew2, const float* __restrict__ eb2,
            const float* __restrict__ fw1, const float* __restrict__ fb1,
            const float* __restrict__ fw2, const float* __restrict__ fb2,
            float* __restrict__ out)
{
    const int g = blockIdx.x * 32 + threadIdx.x;   // 0..4095
    const int grp = g >> 3;                        // chain group 0..511
    const int q = g & 7;                           // lane within group
    const int bA = grp * 2;                        // batch chain A
    const int bB = bA + 1;                         // batch chain B
    const int j0 = q * 4;                          // first hidden unit
    const float C = 2.885390081777927f;            // 2*log2(e)

    // --- Packed register-resident ODE weights for this thread's 4 units ---
    float w1a[4], w1b[4], b1s[4], w2a[4], w2b[4];
    float S0 = 0.f, S1 = 0.f;
#pragma unroll
    for (int i = 0; i < 4; i++) {
        int j = j0 + i;
        w1a[i] = fw1[j]      * C;                  // pre-scaled to exp2 domain
        w1b[i] = fw1[HH + j] * C;
        b1s[i] = fb1[j]      * C;
        w2a[i] = fw2[j * PP + 0];
        w2b[i] = fw2[j * PP + 1];
        S0 += w2a[i];
        S1 += w2b[i];
    }
    if (q == 0) { S0 += fb2[0]; S1 += fb2[1]; }    // fold b2 into one lane

    const u64 W1A01 = pk2(w1a[0], w1a[1]), W1A23 = pk2(w1a[2], w1a[3]);
    const u64 W1B01 = pk2(w1b[0], w1b[1]), W1B23 = pk2(w1b[2], w1b[3]);
    const u64 B01   = pk2(b1s[0], b1s[1]), B23   = pk2(b1s[2], b1s[3]);
    const u64 W2P0 = pk2(w2a[0], w2b[0]), W2P1 = pk2(w2a[1], w2b[1]);
    const u64 W2P2 = pk2(w2a[2], w2b[2]), W2P3 = pk2(w2a[3], w2b[3]);
    const u64 SP   = pk2(S0, S1);
    const u64 NEG2 = pk2(-2.0f, -2.0f);

    // --- Encoder for both chains ---
    float zA1, zA2, zB1, zB2;
    {
        float aA0 = 0.f, aA1 = 0.f, aB0 = 0.f, aB1 = 0.f;
        const float* xA = x + (size_t)bA * TT;
        const float* xB = x + (size_t)bB * TT;
#pragma unroll
        for (int i = 0; i < 4; i++) {
            int j = j0 + i;
            float uA = eb1[j], uB = eb1[j];
#pragma unroll
            for (int l = 0; l < LL; l++) {
                float w = ew1[l * HH + j];
                uA = fmaf(xA[l], w, uA);
                uB = fmaf(xB[l], w, uB);
            }
            float tA = tanh_acc(uA), tB = tanh_acc(uB);
            float v0 = ew2[j * PP + 0], v1 = ew2[j * PP + 1];
            aA0 = fmaf(tA, v0, aA0);  aA1 = fmaf(tA, v1, aA1);
            aB0 = fmaf(tB, v0, aB0);  aB1 = fmaf(tB, v1, aB1);
        }
        zA1 = gsum8(aA0) + eb2[0];
        zA2 = gsum8(aA1) + eb2[1];
        zB1 = gsum8(aB0) + eb2[0];
        zB2 = gsum8(aB1) + eb2[1];
    }

    // z region of d_out: after xhat (B*T) and a (B*T*P) -> offset 3*B*T floats.
    float4* zoA = reinterpret_cast<float4*>(out + 3ull * BB * TT) + (size_t)bA * (TT / 2);
    float4* zoB = reinterpret_cast<float4*>(out + 3ull * BB * TT) + (size_t)bB * (TT / 2);

    // --- One Euler step for BOTH chains, explicitly interleaved ---
    auto STEP2 = [&]() {
        // u-preactivations (packed FFMA2, exp2 domain)
        u64 zzA1 = pk2(zA1, zA1), zzA2 = pk2(zA2, zA2);
        u64 zzB1 = pk2(zB1, zB1), zzB2 = pk2(zB2, zB2);
        u64 uA01 = fma2(zzA1, W1A01, fma2(zzA2, W1B01, B01));
        u64 uB01 = fma2(zzB1, W1A01, fma2(zzB2, W1B01, B01));
        u64 uA23 = fma2(zzA1, W1A23, fma2(zzA2, W1B23, B23));
        u64 uB23 = fma2(zzB1, W1A23, fma2(zzB2, W1B23, B23));
        float uA0, uA1, uA2, uA3, uB0, uB1, uB2, uB3;
        upk2(uA01, uA0, uA1); upk2(uA23, uA2, uA3);
        upk2(uB01, uB0, uB1); upk2(uB23, uB2, uB3);
        // E = exp2(min(u,30)) + 1  (clamp prevents inf -> NaN via pairing)
        float EA0 = ex2f(fminf(uA0, 30.f)) + 1.f;
        float EB0 = ex2f(fminf(uB0, 30.f)) + 1.f;
        float EA1 = ex2f(fminf(uA1, 30.f)) + 1.f;
        float EB1 = ex2f(fminf(uB1, 30.f)) + 1.f;
        float EA2 = ex2f(fminf(uA2, 30.f)) + 1.f;
        float EB2 = ex2f(fminf(uB2, 30.f)) + 1.f;
        float EA3 = ex2f(fminf(uA3, 30.f)) + 1.f;
        float EB3 = ex2f(fminf(uB3, 30.f)) + 1.f;
        // paired reciprocals (one MUFU.RCP per 2 hidden units)
        float prA01 = rcpf(EA0 * EA1), prB01 = rcpf(EB0 * EB1);
        float prA23 = rcpf(EA2 * EA3), prB23 = rcpf(EB2 * EB3);
        float rA0 = prA01 * EA1, rA1 = prA01 * EA0;
        float rB0 = prB01 * EB1, rB1 = prB01 * EB0;
        float rA2 = prA23 * EA3, rA3 = prA23 * EA2;
        float rB2 = prB23 * EB3, rB3 = prB23 * EB2;
        // packed w2 accumulation; tanh = 1-2r trick: p = S - 2*sum(w2*r)
        u64 accA = fma2(pk2(rA1, rA1), W2P1, mul2(pk2(rA0, rA0), W2P0));
        u64 accB = fma2(pk2(rB1, rB1), W2P1, mul2(pk2(rB0, rB0), W2P0));
        accA = fma2(pk2(rA2, rA2), W2P2, accA);
        accB = fma2(pk2(rB2, rB2), W2P2, accB);
        accA = fma2(pk2(rA3, rA3), W2P3, accA);
        accB = fma2(pk2(rB3, rB3), W2P3, accB);
        u64 pA = fma2(accA, NEG2, SP);
        u64 pB = fma2(accB, NEG2, SP);
        float pA0, pA1, pB0, pB1;
        upk2(pA, pA0, pA1); upk2(pB, pB0, pB1);
        // 8-lane reductions: 4 independent gsum8 streams overlap each other
        zA1 += gsum8(pA0);
        zB1 += gsum8(pB0);
        zA2 += gsum8(pA1);
        zB2 += gsum8(pB1);
    };

    // --- 4095 steps, unrolled by 2, one float4 store per 2 time entries ---
#pragma unroll 1
    for (int k = 0; k < 2047; ++k) {
        float aA1s = zA1, aA2s = zA2, aB1s = zB1, aB2s = zB2;  // entries 2k
        STEP2();                                               // entries 2k+1
        if (q == 0) zoA[k] = make_float4(aA1s, aA2s, zA1, zA2);
        if (q == 1) zoB[k] = make_float4(aB1s, aB2s, zB1, zB2);
        STEP2();                                               // entries 2k+2
    }
    {
        float aA1s = zA1, aA2s = zA2, aB1s = zB1, aB2s = zB2;  // entry 4094
        STEP2();                                               // entry 4095
        if (q == 0) zoA[2047] = make_float4(aA1s, aA2s, zA1, zA2);
        if (q == 1) zoB[2047] = make_float4(aB1s, aB2s, zB1, zB2);
    }
}

// ---------------------------------------------------------------------------
// Kernel 2: parallel epilogue. One thread per (b,t).
// kappa = tanh(z); a = [k1*(1-k2), k2]; xhat[t>=P] = a . phi
// ---------------------------------------------------------------------------
__global__ void __launch_bounds__(256)
post_kernel(const float* __restrict__ phi, float* __restrict__ out)
{
    size_t idx = (size_t)blockIdx.x * blockDim.x + threadIdx.x;  // = b*T + t
    if (idx >= (size_t)BB * TT) return;
    int t = (int)(idx & (TT - 1));

    float2 z = reinterpret_cast<const float2*>(out + 3ull * BB * TT)[idx];
    float k1 = tanh_acc(z.x);
    float k2 = tanh_acc(z.y);
    float a0 = k1 * (1.0f - k2);
    float a1 = k2;
    reinterpret_cast<float2*>(out + 1ull * BB * TT)[idx] = make_float2(a0, a1);

    float xh = 0.0f;
    if (t >= PP) {
        float2 ph = reinterpret_cast<const float2*>(phi)[idx];
        xh = fmaf(a0, ph.x, a1 * ph.y);
    }
    out[idx] = xh;
}

// ---------------------------------------------------------------------------
extern "C" void kernel_launch(void* const* d_in, const int* in_sizes, int n_in,
                              void* d_out, int out_size)
{
    const float* x   = (const float*)d_in[0];
    const float* phi = (const float*)d_in[1];
    const float* ew1 = (const float*)d_in[2];
    const float* eb1 = (const float*)d_in[3];
    const float* ew2 = (const float*)d_in[4];
    const float* eb2 = (const float*)d_in[5];
    const float* fw1 = (const float*)d_in[6];
    const float* fb1 = (const float*)d_in[7];
    const float* fw2 = (const float*)d_in[8];
    const float* fb2 = (const float*)d_in[9];
    float* out = (float*)d_out;

    // Scan: 4096 threads = 8 lanes x 2 chains per thread;
    // 128 blocks x 32 threads -> 128 warps, 1 per SMSP across 128 SMs.
    scan_kernel<<<128, 32>>>(x, ew1, eb1, ew2, eb2, fw1, fb1, fw2, fb2, out);

    // Epilogue: one thread per (b,t)
    int nblk = (BB * TT) / 256;
    post_kernel<<<nblk, 256>>>(phi, out);
}

// round 9
// speedup vs baseline: 1.6050x; 1.6050x over previous
#include <cuda_runtime.h>
#include <cstdint>

// Problem constants
#define BB 1024
#define TT 4096
#define LL 30
#define HH 32
#define PP 2

// ---------------------------------------------------------------------------
// MUFU pieces (abs err ~1e-7): tanh(x) = 1 - 2/(exp2(2*log2e*x)+1).
// No clamp needed when each E gets its own rcp: exp2->inf => rcp(inf)=0 =>
// tanh=+1 exactly; exp2->0 => rcp(1)=1 => tanh=-1 exactly.
// ---------------------------------------------------------------------------
__device__ __forceinline__ float ex2f(float x) {
    float r; asm("ex2.approx.ftz.f32 %0, %1;" : "=f"(r) : "f"(x)); return r;
}
__device__ __forceinline__ float rcpf(float x) {
    float r; asm("rcp.approx.ftz.f32 %0, %1;" : "=f"(r) : "f"(x)); return r;
}
__device__ __forceinline__ float tanh_acc(float x) {
    const float C = 2.885390081777927f;  // 2*log2(e)
    float e = ex2f(fminf(x * C, 30.0f));
    return 1.0f - 2.0f * rcpf(e + 1.0f);
}

// ---------------------------------------------------------------------------
// Kernel 1: encoder + sequential Euler scan. (R3 config: proven best.)
// 8 lanes per batch element, 4 hidden units each. Flat-7 butterfly reduction
// (one shuffle latency on the chain). 128 blocks x 64 threads -> 256 warps,
// 1 warp per SMSP across 128 SMs.
// Step math: r_j = rcp(exp2(u_j)+1)  (u pre-scaled by 2*log2e);
//            dz  = S + sum_j w2n_j * r_j   with w2n = -2*w2, S = sum w2 (+b2).
// ---------------------------------------------------------------------------
__global__ void __launch_bounds__(64, 1)
scan_kernel(const float* __restrict__ x,
            const float* __restrict__ ew1, const float* __restrict__ eb1,
            const float* __restrict__ ew2, const float* __restrict__ eb2,
            const float* __restrict__ fw1, const float* __restrict__ fb1,
            const float* __restrict__ fw2, const float* __restrict__ fb2,
            float* __restrict__ out)
{
    const int g = blockIdx.x * 64 + threadIdx.x;   // 0..8191
    const int b = g >> 3;                          // batch element
    const int q = g & 7;                           // lane within chain group
    const int j0 = q * 4;                          // first hidden unit
    const float C = 2.885390081777927f;            // 2*log2(e)

    // --- Register-resident ODE weights for this thread's 4 hidden units ---
    float w1a[4], w1b[4], b1s[4], w2na[4], w2nb[4];
    float S0 = 0.f, S1 = 0.f;                      // per-lane partial of sum(w2)
#pragma unroll
    for (int i = 0; i < 4; i++) {
        int j = j0 + i;
        w1a[i]  = fw1[j]      * C;                 // pre-scaled to exp2 domain
        w1b[i]  = fw1[HH + j] * C;
        b1s[i]  = fb1[j]      * C;
        float a = fw2[j * PP + 0];
        float c = fw2[j * PP + 1];
        w2na[i] = -2.0f * a;
        w2nb[i] = -2.0f * c;
        S0 += a;
        S1 += c;
    }
    if (q == 0) { S0 += fb2[0]; S1 += fb2[1]; }    // fold b2 into one lane

    // --- Encoder: z0 = tanh(x[b,:30] @ ew1 + eb1) @ ew2 + eb2 ---
    float z1, z2;
    {
        float acc0 = 0.f, acc1 = 0.f;
        const float* xb = x + (size_t)b * TT;
#pragma unroll
        for (int i = 0; i < 4; i++) {
            int j = j0 + i;
            float u = eb1[j];
#pragma unroll
            for (int l = 0; l < LL; l++)
                u = fmaf(xb[l], ew1[l * HH + j], u);
            float th = tanh_acc(u);
            acc0 = fmaf(th, ew2[j * PP + 0], acc0);
            acc1 = fmaf(th, ew2[j * PP + 1], acc1);
        }
        acc0 += __shfl_xor_sync(0xffffffffu, acc0, 1);
        acc1 += __shfl_xor_sync(0xffffffffu, acc1, 1);
        acc0 += __shfl_xor_sync(0xffffffffu, acc0, 2);
        acc1 += __shfl_xor_sync(0xffffffffu, acc1, 2);
        acc0 += __shfl_xor_sync(0xffffffffu, acc0, 4);
        acc1 += __shfl_xor_sync(0xffffffffu, acc1, 4);
        z1 = acc0 + eb2[0];
        z2 = acc1 + eb2[1];
    }

    // z region of d_out: after xhat (B*T) and a (B*T*P) -> offset 3*B*T floats.
    float4* zo4 = reinterpret_cast<float4*>(out + 3ull * BB * TT)
                + (size_t)b * (TT / 2);

    // --- One Euler step ---
    auto STEP = [&]() {
        // u_i (exp2 domain), E_i = exp2(u_i)+1, r_i = 1/E_i (own MUFU.RCP)
        float u0 = fmaf(z1, w1a[0], fmaf(z2, w1b[0], b1s[0]));
        float u1 = fmaf(z1, w1a[1], fmaf(z2, w1b[1], b1s[1]));
        float u2 = fmaf(z1, w1a[2], fmaf(z2, w1b[2], b1s[2]));
        float u3 = fmaf(z1, w1a[3], fmaf(z2, w1b[3], b1s[3]));
        float r0 = rcpf(ex2f(u0) + 1.0f);
        float r1 = rcpf(ex2f(u1) + 1.0f);
        float r2 = rcpf(ex2f(u2) + 1.0f);
        float r3 = rcpf(ex2f(u3) + 1.0f);
        // p = S + sum w2n*r, shallow fma trees (depth ~3)
        float p0 = fmaf(r1, w2na[1], fmaf(r0, w2na[0], S0))
                 + fmaf(r3, w2na[3], r2 * w2na[2]);
        float p1 = fmaf(r1, w2nb[1], fmaf(r0, w2nb[0], S1))
                 + fmaf(r3, w2nb[3], r2 * w2nb[2]);
        // flat butterfly over the 8-lane group: 7 independent shuffles of the
        // ORIGINAL value per component -> single shuffle latency on the chain.
        float s01 = __shfl_xor_sync(0xffffffffu, p0, 1);
        float s02 = __shfl_xor_sync(0xffffffffu, p0, 2);
        float s03 = __shfl_xor_sync(0xffffffffu, p0, 3);
        float s04 = __shfl_xor_sync(0xffffffffu, p0, 4);
        float s05 = __shfl_xor_sync(0xffffffffu, p0, 5);
        float s06 = __shfl_xor_sync(0xffffffffu, p0, 6);
        float s07 = __shfl_xor_sync(0xffffffffu, p0, 7);
        float s11 = __shfl_xor_sync(0xffffffffu, p1, 1);
        float s12 = __shfl_xor_sync(0xffffffffu, p1, 2);
        float s13 = __shfl_xor_sync(0xffffffffu, p1, 3);
        float s14 = __shfl_xor_sync(0xffffffffu, p1, 4);
        float s15 = __shfl_xor_sync(0xffffffffu, p1, 5);
        float s16 = __shfl_xor_sync(0xffffffffu, p1, 6);
        float s17 = __shfl_xor_sync(0xffffffffu, p1, 7);
        p0 = ((p0 + s01) + (s02 + s03)) + ((s04 + s05) + (s06 + s07));
        p1 = ((p1 + s11) + (s12 + s13)) + ((s14 + s15) + (s16 + s17));
        z1 += p0;
        z2 += p1;
    };

    // --- 4095 steps, unrolled by 2, one float4 store per 2 time entries ---
#pragma unroll 1
    for (int k = 0; k < 2047; ++k) {
        float az1 = z1, az2 = z2;          // entry 2k
        STEP();                            // entry 2k+1
        if (q == 0) zo4[k] = make_float4(az1, az2, z1, z2);
        STEP();                            // entry 2k+2
    }
    {
        float az1 = z1, az2 = z2;          // entry 4094
        STEP();                            // entry 4095
        if (q == 0) zo4[2047] = make_float4(az1, az2, z1, z2);
    }
}

// ---------------------------------------------------------------------------
// Kernel 2: parallel epilogue. One thread per (b,t).
// kappa = tanh(z); a = [k1*(1-k2), k2]; xhat[t>=P] = a . phi
// ---------------------------------------------------------------------------
__global__ void __launch_bounds__(256)
post_kernel(const float* __restrict__ phi, float* __restrict__ out)
{
    size_t idx = (size_t)blockIdx.x * blockDim.x + threadIdx.x;  // = b*T + t
    if (idx >= (size_t)BB * TT) return;
    int t = (int)(idx & (TT - 1));

    float2 z = reinterpret_cast<const float2*>(out + 3ull * BB * TT)[idx];
    float k1 = tanh_acc(z.x);
    float k2 = tanh_acc(z.y);
    float a0 = k1 * (1.0f - k2);
    float a1 = k2;
    reinterpret_cast<float2*>(out + 1ull * BB * TT)[idx] = make_float2(a0, a1);

    float xh = 0.0f;
    if (t >= PP) {
        float2 ph = reinterpret_cast<const float2*>(phi)[idx];
        xh = fmaf(a0, ph.x, a1 * ph.y);
    }
    out[idx] = xh;
}

// ---------------------------------------------------------------------------
extern "C" void kernel_launch(void* const* d_in, const int* in_sizes, int n_in,
                              void* d_out, int out_size)
{
    const float* x   = (const float*)d_in[0];
    const float* phi = (const float*)d_in[1];
    const float* ew1 = (const float*)d_in[2];
    const float* eb1 = (const float*)d_in[3];
    const float* ew2 = (const float*)d_in[4];
    const float* eb2 = (const float*)d_in[5];
    const float* fw1 = (const float*)d_in[6];
    const float* fb1 = (const float*)d_in[7];
    const float* fw2 = (const float*)d_in[8];
    const float* fb2 = (const float*)d_in[9];
    float* out = (float*)d_out;

    // Scan: 8192 threads = 8 lanes per chain; 128 blocks x 64 threads
    // -> 256 warps, one per SMSP across 128 SMs. (R3-proven placement.)
    scan_kernel<<<128, 64>>>(x, ew1, eb1, ew2, eb2, fw1, fb1, fw2, fb2, out);

    // Epilogue: one thread per (b,t)
    int nblk = (BB * TT) / 256;
    post_kernel<<<nblk, 256>>>(phi, out);
}

// round 10
// speedup vs baseline: 1.9487x; 1.2141x over previous
#include <cuda_runtime.h>
#include <cstdint>

// Problem constants
#define BB 1024
#define TT 4096
#define LL 30
#define HH 32
#define PP 2

// ---------------------------------------------------------------------------
// Accurate tanh (encoder/epilogue only; abs err ~1e-7):
// tanh(x) = 1 - 2/(exp2(2*log2e*x)+1)
// ---------------------------------------------------------------------------
__device__ __forceinline__ float ex2f(float x) {
    float r; asm("ex2.approx.ftz.f32 %0, %1;" : "=f"(r) : "f"(x)); return r;
}
__device__ __forceinline__ float rcpf(float x) {
    float r; asm("rcp.approx.ftz.f32 %0, %1;" : "=f"(r) : "f"(x)); return r;
}
__device__ __forceinline__ float tanh_acc(float x) {
    const float C = 2.885390081777927f;  // 2*log2(e)
    float e = ex2f(fminf(x * C, 30.0f));
    return 1.0f - 2.0f * rcpf(e + 1.0f);
}
// Fast tanh for the scan hot loop: single MUFU.TANH (sm_75+).
__device__ __forceinline__ float tanh_fast(float x) {
    float r; asm("tanh.approx.f32 %0, %1;" : "=f"(r) : "f"(x)); return r;
}

// ---------------------------------------------------------------------------
// Kernel 1: encoder + sequential Euler scan. (R9 placement: proven best.)
// 8 lanes per batch element, 4 hidden units each. Flat-7 butterfly reduction
// (one shuffle latency on the chain). 128 blocks x 64 threads -> 256 warps,
// 1 warp per SMSP across 128 SMs.
// Step math: t_j = tanh.approx(u_j); dz = sum_j w2_j * t_j (+ b2 in lane 0).
// ---------------------------------------------------------------------------
__global__ void __launch_bounds__(64, 1)
scan_kernel(const float* __restrict__ x,
            const float* __restrict__ ew1, const float* __restrict__ eb1,
            const float* __restrict__ ew2, const float* __restrict__ eb2,
            const float* __restrict__ fw1, const float* __restrict__ fb1,
            const float* __restrict__ fw2, const float* __restrict__ fb2,
            float* __restrict__ out)
{
    const int g = blockIdx.x * 64 + threadIdx.x;   // 0..8191
    const int b = g >> 3;                          // batch element
    const int q = g & 7;                           // lane within chain group
    const int j0 = q * 4;                          // first hidden unit

    // --- Register-resident ODE weights for this thread's 4 hidden units ---
    float w1a[4], w1b[4], b1s[4], w2a[4], w2b[4];
#pragma unroll
    for (int i = 0; i < 4; i++) {
        int j = j0 + i;
        w1a[i] = fw1[j];                           // f_w1[0][j] (natural domain)
        w1b[i] = fw1[HH + j];                      // f_w1[1][j]
        b1s[i] = fb1[j];
        w2a[i] = fw2[j * PP + 0];
        w2b[i] = fw2[j * PP + 1];
    }
    // b2 folded into lane 0's accumulation seed
    const float S0 = (q == 0) ? fb2[0] : 0.0f;
    const float S1 = (q == 0) ? fb2[1] : 0.0f;

    // --- Encoder: z0 = tanh(x[b,:30] @ ew1 + eb1) @ ew2 + eb2 (accurate) ---
    float z1, z2;
    {
        float acc0 = 0.f, acc1 = 0.f;
        const float* xb = x + (size_t)b * TT;
#pragma unroll
        for (int i = 0; i < 4; i++) {
            int j = j0 + i;
            float u = eb1[j];
#pragma unroll
            for (int l = 0; l < LL; l++)
                u = fmaf(xb[l], ew1[l * HH + j], u);
            float th = tanh_acc(u);
            acc0 = fmaf(th, ew2[j * PP + 0], acc0);
            acc1 = fmaf(th, ew2[j * PP + 1], acc1);
        }
        acc0 += __shfl_xor_sync(0xffffffffu, acc0, 1);
        acc1 += __shfl_xor_sync(0xffffffffu, acc1, 1);
        acc0 += __shfl_xor_sync(0xffffffffu, acc0, 2);
        acc1 += __shfl_xor_sync(0xffffffffu, acc1, 2);
        acc0 += __shfl_xor_sync(0xffffffffu, acc0, 4);
        acc1 += __shfl_xor_sync(0xffffffffu, acc1, 4);
        z1 = acc0 + eb2[0];
        z2 = acc1 + eb2[1];
    }

    // z region of d_out: after xhat (B*T) and a (B*T*P) -> offset 3*B*T floats.
    float4* zo4 = reinterpret_cast<float4*>(out + 3ull * BB * TT)
                + (size_t)b * (TT / 2);

    // --- One Euler step ---
    auto STEP = [&]() {
        // u_i = w1a_i*z1 + w1b_i*z2 + b1_i ; t_i = tanh.approx(u_i)
        float u0 = fmaf(z1, w1a[0], fmaf(z2, w1b[0], b1s[0]));
        float u1 = fmaf(z1, w1a[1], fmaf(z2, w1b[1], b1s[1]));
        float u2 = fmaf(z1, w1a[2], fmaf(z2, w1b[2], b1s[2]));
        float u3 = fmaf(z1, w1a[3], fmaf(z2, w1b[3], b1s[3]));
        float t0 = tanh_fast(u0);
        float t1 = tanh_fast(u1);
        float t2 = tanh_fast(u2);
        float t3 = tanh_fast(u3);
        // p = sum w2*t (+b2 seed on lane 0), shallow fma trees (depth ~3)
        float p0 = fmaf(t1, w2a[1], fmaf(t0, w2a[0], S0))
                 + fmaf(t3, w2a[3], t2 * w2a[2]);
        float p1 = fmaf(t1, w2b[1], fmaf(t0, w2b[0], S1))
                 + fmaf(t3, w2b[3], t2 * w2b[2]);
        // flat butterfly over the 8-lane group: 7 independent shuffles of the
        // ORIGINAL value per component -> single shuffle latency on the chain.
        float s01 = __shfl_xor_sync(0xffffffffu, p0, 1);
        float s02 = __shfl_xor_sync(0xffffffffu, p0, 2);
        float s03 = __shfl_xor_sync(0xffffffffu, p0, 3);
        float s04 = __shfl_xor_sync(0xffffffffu, p0, 4);
        float s05 = __shfl_xor_sync(0xffffffffu, p0, 5);
        float s06 = __shfl_xor_sync(0xffffffffu, p0, 6);
        float s07 = __shfl_xor_sync(0xffffffffu, p0, 7);
        float s11 = __shfl_xor_sync(0xffffffffu, p1, 1);
        float s12 = __shfl_xor_sync(0xffffffffu, p1, 2);
        float s13 = __shfl_xor_sync(0xffffffffu, p1, 3);
        float s14 = __shfl_xor_sync(0xffffffffu, p1, 4);
        float s15 = __shfl_xor_sync(0xffffffffu, p1, 5);
        float s16 = __shfl_xor_sync(0xffffffffu, p1, 6);
        float s17 = __shfl_xor_sync(0xffffffffu, p1, 7);
        p0 = ((p0 + s01) + (s02 + s03)) + ((s04 + s05) + (s06 + s07));
        p1 = ((p1 + s11) + (s12 + s13)) + ((s14 + s15) + (s16 + s17));
        z1 += p0;
        z2 += p1;
    };

    // --- 4095 steps, unrolled by 2, one float4 store per 2 time entries ---
#pragma unroll 1
    for (int k = 0; k < 2047; ++k) {
        float az1 = z1, az2 = z2;          // entry 2k
        STEP();                            // entry 2k+1
        if (q == 0) zo4[k] = make_float4(az1, az2, z1, z2);
        STEP();                            // entry 2k+2
    }
    {
        float az1 = z1, az2 = z2;          // entry 4094
        STEP();                            // entry 4095
        if (q == 0) zo4[2047] = make_float4(az1, az2, z1, z2);
    }
}

// ---------------------------------------------------------------------------
// Kernel 2: parallel epilogue. One thread per (b,t). (Accurate tanh.)
// kappa = tanh(z); a = [k1*(1-k2), k2]; xhat[t>=P] = a . phi
// ---------------------------------------------------------------------------
__global__ void __launch_bounds__(256)
post_kernel(const float* __restrict__ phi, float* __restrict__ out)
{
    size_t idx = (size_t)blockIdx.x * blockDim.x + threadIdx.x;  // = b*T + t
    if (idx >= (size_t)BB * TT) return;
    int t = (int)(idx & (TT - 1));

    float2 z = reinterpret_cast<const float2*>(out + 3ull * BB * TT)[idx];
    float k1 = tanh_acc(z.x);
    float k2 = tanh_acc(z.y);
    float a0 = k1 * (1.0f - k2);
    float a1 = k2;
    reinterpret_cast<float2*>(out + 1ull * BB * TT)[idx] = make_float2(a0, a1);

    float xh = 0.0f;
    if (t >= PP) {
        float2 ph = reinterpret_cast<const float2*>(phi)[idx];
        xh = fmaf(a0, ph.x, a1 * ph.y);
    }
    out[idx] = xh;
}

// ---------------------------------------------------------------------------
extern "C" void kernel_launch(void* const* d_in, const int* in_sizes, int n_in,
                              void* d_out, int out_size)
{
    const float* x   = (const float*)d_in[0];
    const float* phi = (const float*)d_in[1];
    const float* ew1 = (const float*)d_in[2];
    const float* eb1 = (const float*)d_in[3];
    const float* ew2 = (const float*)d_in[4];
    const float* eb2 = (const float*)d_in[5];
    const float* fw1 = (const float*)d_in[6];
    const float* fb1 = (const float*)d_in[7];
    const float* fw2 = (const float*)d_in[8];
    const float* fb2 = (const float*)d_in[9];
    float* out = (float*)d_out;

    // Scan: 8192 threads = 8 lanes per chain; 128 blocks x 64 threads
    // -> 256 warps, one per SMSP across 128 SMs. (R9-proven placement.)
    scan_kernel<<<128, 64>>>(x, ew1, eb1, ew2, eb2, fw1, fb1, fw2, fb2, out);

    // Epilogue: one thread per (b,t)
    int nblk = (BB * TT) / 256;
    post_kernel<<<nblk, 256>>>(phi, out);
}